// round 11
// baseline (speedup 1.0000x reference)
#include <cuda_runtime.h>
#include <cuda_bf16.h>
#include <cuda_fp16.h>
#include <cstdint>

#define NNODES 100000
#define NEDGES 3200000

// ------------------------- device scratch (no allocs) -----------------------
__device__ __align__(16) __half g_ky[(size_t)NNODES * 64];
__device__ __align__(16) float  g_sums[(size_t)NNODES * 64];
__device__ __align__(16) float  g_v[(size_t)NNODES * 64];
__device__ float g_cnt[NNODES];
// pre-split, transposed (t-major), SW128-swizzled W2 tiles:
// [ki][c] -> 256 rows (t) x 64 cols (m) bf16, 128B/row, 32KB per tile
__device__ __align__(16) __nv_bfloat16 g_Bh[2 * 4 * 256 * 64];
__device__ __align__(16) __nv_bfloat16 g_Bl[2 * 4 * 256 * 64];

#define SWZ(o) ((o) ^ (((o) >> 3) & 0x70))

__device__ __forceinline__ uint32_t smem_u32(const void* p) {
    uint32_t a;
    asm("{ .reg .u64 t; cvta.to.shared.u64 t, %1; cvt.u32.u64 %0, t; }"
        : "=r"(a) : "l"(p));
    return a;
}
__device__ __forceinline__ void ldsm_x4(uint32_t* r, uint32_t a) {
    asm volatile("ldmatrix.sync.aligned.m8n8.x4.shared.b16 {%0,%1,%2,%3}, [%4];"
                 : "=r"(r[0]), "=r"(r[1]), "=r"(r[2]), "=r"(r[3]) : "r"(a));
}
__device__ __forceinline__ void mma16816(float* d, const uint32_t* a, const uint32_t* b) {
    asm volatile("mma.sync.aligned.m16n8k16.row.col.f32.bf16.bf16.f32 "
                 "{%0,%1,%2,%3}, {%4,%5,%6,%7}, {%8,%9}, {%0,%1,%2,%3};"
                 : "+f"(d[0]), "+f"(d[1]), "+f"(d[2]), "+f"(d[3])
                 : "r"(a[0]), "r"(a[1]), "r"(a[2]), "r"(a[3]),
                   "r"(b[0]), "r"(b[1]));
}
__device__ __forceinline__ void cpasync16(uint32_t dst, const void* src) {
    asm volatile("cp.async.ca.shared.global [%0], [%1], 16;" :: "r"(dst), "l"(src));
}
#define CP_COMMIT() asm volatile("cp.async.commit_group;" ::: "memory")
#define CP_WAIT0()  asm volatile("cp.async.wait_group 0;" ::: "memory")

// SMEM layout (bytes): AH 8K | AL 8K | B (Bh 32K + Bl 32K) | ys 17408
#define SM_AH    0
#define SM_AL    8192
#define SM_B     16384
#define SM_YS    81920
#define SM_TOTAL 99328

// ---------------- prep (W2 -> split/transposed/swizzled tiles) + zero -------
__global__ void __launch_bounds__(256)
prep_zero(const float* __restrict__ W2a, const float* __restrict__ W2b) {
    int id = blockIdx.x * blockDim.x + threadIdx.x;   // 1.6M threads
    if (id < NNODES * 16)
        ((float4*)g_sums)[id] = make_float4(0.f, 0.f, 0.f, 0.f);
    if (id < NNODES)
        g_cnt[id] = 0.f;
    if (id < 131072) {
        int ki = id >> 16;
        int r  = id & 65535;
        int c  = r >> 14;
        int t  = (r >> 6) & 255;
        int m  = r & 63;
        const float* W2 = ki ? W2b : W2a;
        float w = W2[m * 1024 + c * 256 + t];
        __nv_bfloat16 hi = __float2bfloat16(w);
        __nv_bfloat16 lo = __float2bfloat16(w - __bfloat162float(hi));
        uint32_t off = SWZ((uint32_t)(t * 128 + m * 2));
        size_t tb = (size_t)(ki * 4 + c) * 32768;
        *(__nv_bfloat16*)((char*)g_Bh + tb + off) = hi;
        *(__nv_bfloat16*)((char*)g_Bl + tb + off) = lo;
    }
}

// ------------------------- fused HMMA pass ----------------------------------
// 64 nodes/CTA, 8 warps, 2 CTAs/SM. Warp tile: 32 rows (rb) x 8 n-tiles
// (par = j-half, qsel = k-half). Drain-per-(ks,qp): y += x_k * D_partial
// (legal since epilogue is linear in D). qsel pair combines via smem ys.
// D = Ah@Bh^T + Ah@Bl^T + Al@Bh^T (fp32 acc). b2 pre-contracted into y init.
template<bool DIVCNT, bool STOREHALF>
__global__ void __launch_bounds__(256, 2)
mma_fused(const float* __restrict__ xin, const float* __restrict__ ea,
          const float* __restrict__ W1,  const float* __restrict__ b1,
          const float* __restrict__ b2,  const float* __restrict__ cnt,
          float* __restrict__ fout, __half* __restrict__ hout, int ki)
{
    extern __shared__ char smem[];
    const uint32_t smb = smem_u32(smem);
    float* ys = (float*)(smem + SM_YS);
    const int tid = threadIdx.x, wid = tid >> 5, lid = tid & 31;
    const int nb0 = blockIdx.x * 64;

    // kick off B[0] staging immediately (overlaps with h MLP)
    {
        const char* sh = (const char*)g_Bh + (size_t)(ki * 4) * 32768;
        const char* sl = (const char*)g_Bl + (size_t)(ki * 4) * 32768;
        #pragma unroll
        for (int i = 0; i < 8; i++) {
            uint32_t o = (uint32_t)(tid * 16 + i * 4096);
            cpasync16(smb + SM_B + o, sh + o);
            cpasync16(smb + SM_B + 32768u + o, sl + o);
        }
        CP_COMMIT();
    }

    // ---- h = relu(ea@W1+b1), bf16 split into A tiles. thread: node tid>>2 ----
    {
        int n = tid >> 2, gn = nb0 + n, mb = (tid & 3) * 16;
        float e0 = 0.f, e1 = 0.f, e2 = 0.f;
        if (gn < NNODES) { e0 = ea[gn*3]; e1 = ea[gn*3+1]; e2 = ea[gn*3+2]; }
        #pragma unroll
        for (int q = 0; q < 16; q++) {
            int m = mb + q;
            float h = 0.f;
            if (gn < NNODES)
                h = fmaxf(fmaf(e2, W1[128+m], fmaf(e1, W1[64+m], fmaf(e0, W1[m], b1[m]))), 0.f);
            __nv_bfloat16 hi = __float2bfloat16(h);
            __nv_bfloat16 lo = __float2bfloat16(h - __bfloat162float(hi));
            uint32_t off = SWZ((uint32_t)(n * 128 + m * 2));
            *(__nv_bfloat16*)(smem + SM_AH + off) = hi;
            *(__nv_bfloat16*)(smem + SM_AL + off) = lo;
        }
    }

    const int rb   = wid & 1;          // row block (32 rows)
    const int par  = (wid >> 1) & 1;   // j half
    const int qsel = wid >> 2;         // k half (0: k 0-7, 1: k 8-15)
    const uint32_t acol  = (uint32_t)(((lid >> 4) & 1) * 8);
    const uint32_t arow0 = (uint32_t)(rb * 32 + (lid & 7) + ((lid >> 3) & 1) * 8);
    const int bsel  = ((lid >> 4) & 1) * 2;
    const int brow8 = lid & 7;
    const int bkoff = ((lid >> 3) & 1) * 8;
    const int jlo = (lid & 3) * 2;

    int rowg[4]; float rcs[4];
    #pragma unroll
    for (int g = 0; g < 4; g++) {          // g = mt*2 + rh
        rowg[g] = rb * 32 + (g >> 1) * 16 + (g & 1) * 8 + (lid >> 2);
        int gn = nb0 + rowg[g];
        float r = 1.f;
        if (DIVCNT && gn < NNODES) r = 1.f / fmaxf(cnt[gn], 1.f);
        rcs[g] = r;
    }

    CP_WAIT0();
    __syncthreads();   // B[0] + A tiles staged

    for (int c = 0; c < 4; c++) {
        // ---- load x slice (8 k's of this qsel) and pre-contract b2 ----
        float xk[4][8];
        #pragma unroll
        for (int g = 0; g < 4; g++) {
            int gn = nb0 + rowg[g];
            if (gn < NNODES) {
                float4 a = *(const float4*)(xin + (size_t)gn*64 + c*16 + qsel*8);
                float4 b = *(const float4*)(xin + (size_t)gn*64 + c*16 + qsel*8 + 4);
                xk[g][0]=a.x*rcs[g]; xk[g][1]=a.y*rcs[g]; xk[g][2]=a.z*rcs[g]; xk[g][3]=a.w*rcs[g];
                xk[g][4]=b.x*rcs[g]; xk[g][5]=b.y*rcs[g]; xk[g][6]=b.z*rcs[g]; xk[g][7]=b.w*rcs[g];
            } else {
                #pragma unroll
                for (int q = 0; q < 8; q++) xk[g][q] = 0.f;
            }
        }
        float y[4][2];
        #pragma unroll
        for (int g = 0; g < 4; g++) { y[g][0] = 0.f; y[g][1] = 0.f; }
        #pragma unroll
        for (int kl = 0; kl < 8; kl++) {
            int t0 = c*256 + (qsel*8 + kl)*16 + 8*par + jlo;
            float b2a = b2[t0], b2b = b2[t0 + 1];
            #pragma unroll
            for (int g = 0; g < 4; g++) {
                y[g][0] = fmaf(xk[g][kl], b2a, y[g][0]);
                y[g][1] = fmaf(xk[g][kl], b2b, y[g][1]);
            }
        }

        // ---- mainloop: per ks, per qp (2 k's): 12 mma + drain ----
        #pragma unroll
        for (int ks = 0; ks < 4; ks++) {
            uint32_t ah[2][4], al[2][4];
            #pragma unroll
            for (int mt = 0; mt < 2; mt++) {
                uint32_t aoff = (arow0 + mt*16) * 128u + (ks*16 + acol) * 2u;
                ldsm_x4(ah[mt], smb + SM_AH + SWZ(aoff));
                ldsm_x4(al[mt], smb + SM_AL + SWZ(aoff));
            }
            #pragma unroll
            for (int qp = 0; qp < 4; qp++) {
                int nts = (qsel*8 + qp*2) * 2 + par + bsel;
                uint32_t boff = (uint32_t)(nts * 8 + brow8) * 128u
                              + (uint32_t)(ks*16 + bkoff) * 2u;
                uint32_t bh4[4], bl4[4];
                ldsm_x4(bh4, smb + SM_B + SWZ(boff));
                ldsm_x4(bl4, smb + SM_B + 32768u + SWZ(boff));
                float acc[2][2][4];
                #pragma unroll
                for (int mt = 0; mt < 2; mt++)
                    #pragma unroll
                    for (int kk = 0; kk < 2; kk++)
                        #pragma unroll
                        for (int e = 0; e < 4; e++) acc[mt][kk][e] = 0.f;
                #pragma unroll
                for (int mt = 0; mt < 2; mt++) {
                    mma16816(acc[mt][0], ah[mt], bh4);
                    mma16816(acc[mt][0], ah[mt], bl4);
                    mma16816(acc[mt][0], al[mt], bh4);
                    mma16816(acc[mt][1], ah[mt], bh4 + 2);
                    mma16816(acc[mt][1], ah[mt], bl4 + 2);
                    mma16816(acc[mt][1], al[mt], bh4 + 2);
                }
                // drain: y[g] += xk[g][k] * acc
                #pragma unroll
                for (int mt = 0; mt < 2; mt++)
                    #pragma unroll
                    for (int kk = 0; kk < 2; kk++) {
                        float xa = 0, xb = 0, xc_ = 0, xd = 0;
                        int klc = qp*2 + kk;
                        xa = xk[mt*2 + 0][klc];
                        xb = xk[mt*2 + 1][klc];
                        y[mt*2+0][0] = fmaf(xa, acc[mt][kk][0], y[mt*2+0][0]);
                        y[mt*2+0][1] = fmaf(xa, acc[mt][kk][1], y[mt*2+0][1]);
                        y[mt*2+1][0] = fmaf(xb, acc[mt][kk][2], y[mt*2+1][0]);
                        y[mt*2+1][1] = fmaf(xb, acc[mt][kk][3], y[mt*2+1][1]);
                        (void)xc_; (void)xd;
                    }
            }
        }

        // ---- qsel combine via ys, overlap next-channel staging ----
        if (qsel == 0) {
            #pragma unroll
            for (int g = 0; g < 4; g++) {
                float* yp = ys + rowg[g] * 68 + c * 16 + 8 * par + jlo;
                yp[0] = y[g][0]; yp[1] = y[g][1];
            }
        }
        __syncthreads();   // LDSM of B[c] done + ys(qsel0) written

        if (c < 3) {       // stage B[c+1] (B buffer now safe to overwrite)
            const char* sh = (const char*)g_Bh + (size_t)(ki * 4 + c + 1) * 32768;
            const char* sl = (const char*)g_Bl + (size_t)(ki * 4 + c + 1) * 32768;
            #pragma unroll
            for (int i = 0; i < 8; i++) {
                uint32_t o = (uint32_t)(tid * 16 + i * 4096);
                cpasync16(smb + SM_B + o, sh + o);
                cpasync16(smb + SM_B + 32768u + o, sl + o);
            }
            CP_COMMIT();
        }

        if (qsel == 1) {
            #pragma unroll
            for (int g = 0; g < 4; g++) {
                int gn = nb0 + rowg[g];
                if (gn < NNODES) {
                    const float* yp = ys + rowg[g] * 68 + c * 16 + 8 * par + jlo;
                    float r0 = yp[0] + y[g][0];
                    float r1 = yp[1] + y[g][1];
                    if (STOREHALF)
                        *(__half2*)(hout + (size_t)gn*64 + c*16 + 8*par + jlo) =
                            __floats2half2_rn(r0, r1);
                    else
                        *(float2*)(fout + (size_t)gn*64 + c*16 + 8*par + jlo) =
                            make_float2(r0, r1);
                }
            }
        }

        if (c < 3) {
            CP_WAIT0();
            __syncthreads();   // B[c+1] staged + ys read complete
        }
    }
}

// ------------------------- scatter-sum over edges (ILP x8, fp16 gather) -----
__global__ void __launch_bounds__(256)
scatter_kernel(const int* __restrict__ ei) {
    const int QE = NEDGES / 8;                       // 400000
    int t = blockIdx.x * blockDim.x + threadIdx.x;
    if (t >= QE * 16) return;
    int e0 = t >> 4, q = t & 15;
    int dst[8], src[8];
    #pragma unroll
    for (int i = 0; i < 8; i++) {
        int e = e0 + i * QE;
        dst[i] = ei[e];
        src[i] = ei[NEDGES + e];
    }
    float4 v[8];
    #pragma unroll
    for (int i = 0; i < 8; i++) {
        uint2 u = *(const uint2*)((const __half*)g_ky + (size_t)src[i] * 64 + q * 4);
        float2 f0 = __half22float2(*(__half2*)&u.x);
        float2 f1 = __half22float2(*(__half2*)&u.y);
        v[i] = make_float4(f0.x, f0.y, f1.x, f1.y);
    }
    #pragma unroll
    for (int i = 0; i < 8; i++)
        atomicAdd(&((float4*)g_sums)[(size_t)dst[i] * 16 + q], v[i]);
    if (q == 0) {
        #pragma unroll
        for (int i = 0; i < 8; i++)
            atomicAdd(&g_cnt[dst[i]], 1.0f);
    }
}

// ------------------------- mix linear: out = v @ mixW^T + mixb --------------
__global__ void __launch_bounds__(256)
mix_kernel(const float* __restrict__ mixW, const float* __restrict__ mixb,
           float* __restrict__ out)
{
    __shared__ float mWs[4096];
    int tid = threadIdx.x;
    for (int i = tid; i < 1024; i += 256)
        ((float4*)mWs)[i] = ((const float4*)mixW)[i];
    __syncthreads();

    int n = blockIdx.x * 128 + (tid >> 1);
    int ob = (tid & 1) * 32;
    if (n >= NNODES) return;
    const float4* v4 = (const float4*)(g_v + (size_t)n * 64);
    const float4* mw4 = (const float4*)mWs;
    float a2[32];
    #pragma unroll
    for (int o = 0; o < 32; o++) a2[o] = 0.f;
    #pragma unroll 4
    for (int v = 0; v < 16; v++) {
        float4 yv = v4[v];
        #pragma unroll
        for (int o = 0; o < 32; o++) {
            float4 w4 = mw4[(ob + o) * 16 + v];
            a2[o] = fmaf(yv.x, w4.x, a2[o]);
            a2[o] = fmaf(yv.y, w4.y, a2[o]);
            a2[o] = fmaf(yv.z, w4.z, a2[o]);
            a2[o] = fmaf(yv.w, w4.w, a2[o]);
        }
    }
    #pragma unroll
    for (int o = 0; o < 32; o++)
        out[(size_t)n * 64 + ob + o] = a2[o] + mixb[ob + o];
}

// -----------------------------------------------------------------------------
extern "C" void kernel_launch(void* const* d_in, const int* in_sizes, int n_in,
                              void* d_out, int out_size)
{
    const float* x    = (const float*)d_in[0];
    const float* ea   = (const float*)d_in[1];
    const int*   ei   = (const int*)  d_in[2];
    const float* k1W1 = (const float*)d_in[3];
    const float* k1b1 = (const float*)d_in[4];
    const float* k1W2 = (const float*)d_in[5];
    const float* k1b2 = (const float*)d_in[6];
    const float* k2W1 = (const float*)d_in[7];
    const float* k2b1 = (const float*)d_in[8];
    const float* k2W2 = (const float*)d_in[9];
    const float* k2b2 = (const float*)d_in[10];
    const float* mixW = (const float*)d_in[11];
    const float* mixb = (const float*)d_in[12];
    float* out = (float*)d_out;

    __half* ky_p = nullptr; float *sums_p = nullptr, *cnt_p = nullptr, *v_p = nullptr;
    cudaGetSymbolAddress((void**)&ky_p,   g_ky);
    cudaGetSymbolAddress((void**)&sums_p, g_sums);
    cudaGetSymbolAddress((void**)&cnt_p,  g_cnt);
    cudaGetSymbolAddress((void**)&v_p,    g_v);

    cudaFuncSetAttribute((const void*)mma_fused<false, true>,
                         cudaFuncAttributeMaxDynamicSharedMemorySize, SM_TOTAL);
    cudaFuncSetAttribute((const void*)mma_fused<true, false>,
                         cudaFuncAttributeMaxDynamicSharedMemorySize, SM_TOTAL);

    const int grid = (NNODES + 63) / 64;      // 1563

    prep_zero<<<(NNODES * 16 + 255) / 256, 256>>>(k1W2, k2W2);

    mma_fused<false, true><<<grid, 256, SM_TOTAL>>>(
        x, ea, k1W1, k1b1, k1b2, nullptr, nullptr, ky_p, 0);

    scatter_kernel<<<(NEDGES / 8 * 16 + 255) / 256, 256>>>(ei);

    mma_fused<true, false><<<grid, 256, SM_TOTAL>>>(
        sums_p, ea, k2W1, k2b1, k2b2, cnt_p, v_p, nullptr, 1);

    mix_kernel<<<(NNODES + 127) / 128, 256>>>(mixW, mixb, out);
}

// round 12
// speedup vs baseline: 1.5678x; 1.5678x over previous
#include <cuda_runtime.h>
#include <cuda_bf16.h>
#include <cuda_fp16.h>
#include <cstdint>

#define NNODES 100000
#define NEDGES 3200000

// ------------------------- device scratch (no allocs) -----------------------
__device__ __align__(16) __half g_ky[(size_t)NNODES * 64];
__device__ __align__(16) float  g_sums[(size_t)NNODES * 64];
__device__ __align__(16) float  g_v[(size_t)NNODES * 64];
__device__ float g_cnt[NNODES];
// pre-split, transposed (t-major), SW128-swizzled W2 tiles:
// [ki][c] -> 256 rows (t) x 64 cols (m) bf16, 128B/row, 32KB per tile
__device__ __align__(16) __nv_bfloat16 g_Bh[2 * 4 * 256 * 64];
__device__ __align__(16) __nv_bfloat16 g_Bl[2 * 4 * 256 * 64];

#define SWZ(o) ((o) ^ (((o) >> 3) & 0x70))

__device__ __forceinline__ uint32_t smem_u32(const void* p) {
    uint32_t a;
    asm("{ .reg .u64 t; cvta.to.shared.u64 t, %1; cvt.u32.u64 %0, t; }"
        : "=r"(a) : "l"(p));
    return a;
}
__device__ __forceinline__ void ldsm_x4(uint32_t* r, uint32_t a) {
    asm volatile("ldmatrix.sync.aligned.m8n8.x4.shared.b16 {%0,%1,%2,%3}, [%4];"
                 : "=r"(r[0]), "=r"(r[1]), "=r"(r[2]), "=r"(r[3]) : "r"(a));
}
__device__ __forceinline__ void mma16816(float* d, const uint32_t* a, const uint32_t* b) {
    asm volatile("mma.sync.aligned.m16n8k16.row.col.f32.bf16.bf16.f32 "
                 "{%0,%1,%2,%3}, {%4,%5,%6,%7}, {%8,%9}, {%0,%1,%2,%3};"
                 : "+f"(d[0]), "+f"(d[1]), "+f"(d[2]), "+f"(d[3])
                 : "r"(a[0]), "r"(a[1]), "r"(a[2]), "r"(a[3]),
                   "r"(b[0]), "r"(b[1]));
}
__device__ __forceinline__ void cpasync16(uint32_t dst, const void* src) {
    asm volatile("cp.async.ca.shared.global [%0], [%1], 16;" :: "r"(dst), "l"(src));
}
#define CP_COMMIT() asm volatile("cp.async.commit_group;" ::: "memory")
#define CP_WAIT1()  asm volatile("cp.async.wait_group 1;" ::: "memory")
#define CP_WAIT0()  asm volatile("cp.async.wait_group 0;" ::: "memory")

// SMEM layout (bytes): AH 8K | AL 8K | Bh 32K | Bl 32K
#define SM_AH    0
#define SM_AL    8192
#define SM_B     16384
#define SM_TOTAL 81920

// ---------------- prep (W2 -> split/transposed/swizzled tiles) + zero -------
__global__ void __launch_bounds__(256)
prep_zero(const float* __restrict__ W2a, const float* __restrict__ W2b) {
    int id = blockIdx.x * blockDim.x + threadIdx.x;   // 1.6M threads
    if (id < NNODES * 16)
        ((float4*)g_sums)[id] = make_float4(0.f, 0.f, 0.f, 0.f);
    if (id < NNODES)
        g_cnt[id] = 0.f;
    if (id < 131072) {
        int ki = id >> 16;
        int r  = id & 65535;
        int c  = r >> 14;
        int t  = (r >> 6) & 255;
        int m  = r & 63;
        const float* W2 = ki ? W2b : W2a;
        float w = W2[m * 1024 + c * 256 + t];
        __nv_bfloat16 hi = __float2bfloat16(w);
        __nv_bfloat16 lo = __float2bfloat16(w - __bfloat162float(hi));
        uint32_t off = SWZ((uint32_t)(t * 128 + m * 2));
        size_t tb = (size_t)(ki * 4 + c) * 32768;
        *(__nv_bfloat16*)((char*)g_Bh + tb + off) = hi;
        *(__nv_bfloat16*)((char*)g_Bl + tb + off) = lo;
    }
}

// 32KB half-tile staging (256 threads x 16B x 8)
__device__ __forceinline__ void stage_half(uint32_t dst, const char* src, int tid) {
    #pragma unroll
    for (int i = 0; i < 8; i++) {
        uint32_t o = (uint32_t)(tid * 16 + i * 4096);
        cpasync16(dst + o, src + o);
    }
}

// ------------------------- fused HMMA pass ----------------------------------
// 64 nodes/CTA, 8 warps, 2 CTAs/SM. Warp: rb=wid&3 (16 rows), par=wid>>2
// (j-half, all 16 k) -> warp-local epilogue. Per channel, two sweeps:
//   Bh-sweep: acc = Ah@Bh^T + Al@Bh^T   (drain y += x*(acc+b2) per qh)
//   Bl-sweep: acc = Ah@Bl^T             (drain y += x*acc per qh)
// Bh buffer freed mid-channel -> Bh[c+1] staging overlaps Bl-sweeps;
// Bl[c+1] staging overlaps next channel's Bh-sweeps (latency hidden).
template<bool DIVCNT, bool STOREHALF>
__global__ void __launch_bounds__(256, 2)
mma_fused(const float* __restrict__ xin, const float* __restrict__ ea,
          const float* __restrict__ W1,  const float* __restrict__ b1,
          const float* __restrict__ b2,  const float* __restrict__ cnt,
          float* __restrict__ fout, __half* __restrict__ hout, int ki)
{
    extern __shared__ char smem[];
    const uint32_t smb = smem_u32(smem);
    const int tid = threadIdx.x, wid = tid >> 5, lid = tid & 31;
    const int nb0 = blockIdx.x * 64;

    // stage Bh[0], Bl[0] (overlaps h MLP)
    stage_half(smb + SM_B,          (const char*)g_Bh + (size_t)(ki*4) * 32768, tid);
    CP_COMMIT();
    stage_half(smb + SM_B + 32768u, (const char*)g_Bl + (size_t)(ki*4) * 32768, tid);
    CP_COMMIT();

    // ---- h = relu(ea@W1+b1), bf16 split into A tiles. thread: node tid>>2 ----
    {
        int n = tid >> 2, gn = nb0 + n, mb = (tid & 3) * 16;
        float e0 = 0.f, e1 = 0.f, e2 = 0.f;
        if (gn < NNODES) { e0 = ea[gn*3]; e1 = ea[gn*3+1]; e2 = ea[gn*3+2]; }
        #pragma unroll
        for (int q = 0; q < 16; q++) {
            int m = mb + q;
            float h = 0.f;
            if (gn < NNODES)
                h = fmaxf(fmaf(e2, W1[128+m], fmaf(e1, W1[64+m], fmaf(e0, W1[m], b1[m]))), 0.f);
            __nv_bfloat16 hi = __float2bfloat16(h);
            __nv_bfloat16 lo = __float2bfloat16(h - __bfloat162float(hi));
            uint32_t off = SWZ((uint32_t)(n * 128 + m * 2));
            *(__nv_bfloat16*)(smem + SM_AH + off) = hi;
            *(__nv_bfloat16*)(smem + SM_AL + off) = lo;
        }
    }

    const int rb = wid & 3, par = wid >> 2;
    const uint32_t arow = (uint32_t)(rb * 16 + (lid & 7) + ((lid >> 3) & 1) * 8);
    const uint32_t acol = (uint32_t)(((lid >> 4) & 1) * 8);
    const int bsel  = ((lid >> 4) & 1) * 2;
    const int brow8 = lid & 7;
    const int bkoff = ((lid >> 3) & 1) * 8;
    const int jlo   = (lid & 3) * 2;

    int rowg[2]; float rcs[2];
    #pragma unroll
    for (int g = 0; g < 2; g++) {
        rowg[g] = rb * 16 + g * 8 + (lid >> 2);
        int gn = nb0 + rowg[g];
        float r = 1.f;
        if (DIVCNT && gn < NNODES) r = 1.f / fmaxf(cnt[gn], 1.f);
        rcs[g] = r;
    }

    for (int c = 0; c < 4; c++) {
        CP_WAIT1();          // Bh[c] staged (Bl[c] may be in flight)
        __syncthreads();     // + A tiles visible (first iter)

        // hoist Ah frags for all ks (reused by both sweeps)
        uint32_t ah[4][4];
        #pragma unroll
        for (int ks = 0; ks < 4; ks++) {
            uint32_t aoff = arow * 128u + (ks * 16 + acol) * 2u;
            ldsm_x4(ah[ks], smb + SM_AH + SWZ(aoff));
        }

        float y[2][2];
        y[0][0] = y[0][1] = y[1][0] = y[1][1] = 0.f;

        // ======== Bh sweep: Ah@Bh + Al@Bh ========
        #pragma unroll
        for (int qh = 0; qh < 2; qh++) {
            float acc[8][4];
            #pragma unroll
            for (int qq = 0; qq < 8; qq++)
                #pragma unroll
                for (int e = 0; e < 4; e++) acc[qq][e] = 0.f;
            #pragma unroll
            for (int ks = 0; ks < 4; ks++) {
                uint32_t al4[4];
                uint32_t aoff = arow * 128u + (ks * 16 + acol) * 2u;
                ldsm_x4(al4, smb + SM_AL + SWZ(aoff));
                #pragma unroll
                for (int qp = 0; qp < 4; qp++) {
                    int nts = (qh*8 + qp*2) * 2 + par + bsel;
                    uint32_t boff = (uint32_t)(nts * 8 + brow8) * 128u
                                  + (uint32_t)(ks*16 + bkoff) * 2u;
                    uint32_t bh4[4];
                    ldsm_x4(bh4, smb + SM_B + SWZ(boff));
                    mma16816(acc[qp*2],     ah[ks], bh4);
                    mma16816(acc[qp*2],     al4,    bh4);
                    mma16816(acc[qp*2 + 1], ah[ks], bh4 + 2);
                    mma16816(acc[qp*2 + 1], al4,    bh4 + 2);
                }
            }
            // drain (with b2): y += x * (acc + b2)
            #pragma unroll
            for (int g = 0; g < 2; g++) {
                int gn = nb0 + rowg[g];
                float xk[8];
                #pragma unroll
                for (int q = 0; q < 8; q++) xk[q] = 0.f;
                if (gn < NNODES) {
                    float4 a = *(const float4*)(xin + (size_t)gn*64 + c*16 + qh*8);
                    float4 b = *(const float4*)(xin + (size_t)gn*64 + c*16 + qh*8 + 4);
                    xk[0]=a.x*rcs[g]; xk[1]=a.y*rcs[g]; xk[2]=a.z*rcs[g]; xk[3]=a.w*rcs[g];
                    xk[4]=b.x*rcs[g]; xk[5]=b.y*rcs[g]; xk[6]=b.z*rcs[g]; xk[7]=b.w*rcs[g];
                }
                #pragma unroll
                for (int qq = 0; qq < 8; qq++) {
                    int t0 = c*256 + (qh*8 + qq)*16 + 8*par + jlo;
                    y[g][0] = fmaf(xk[qq], acc[qq][g*2]     + b2[t0],     y[g][0]);
                    y[g][1] = fmaf(xk[qq], acc[qq][g*2 + 1] + b2[t0 + 1], y[g][1]);
                }
            }
        }

        CP_WAIT0();          // Bl[c] staged
        __syncthreads();     // all warps done reading Bh[c] -> Bh buffer free
        if (c < 3) {
            stage_half(smb + SM_B, (const char*)g_Bh + (size_t)(ki*4 + c + 1) * 32768, tid);
            CP_COMMIT();     // overlaps Bl sweeps below
        }

        // ======== Bl sweep: Ah@Bl ========
        #pragma unroll
        for (int qh = 0; qh < 2; qh++) {
            float acc[8][4];
            #pragma unroll
            for (int qq = 0; qq < 8; qq++)
                #pragma unroll
                for (int e = 0; e < 4; e++) acc[qq][e] = 0.f;
            #pragma unroll
            for (int ks = 0; ks < 4; ks++) {
                #pragma unroll
                for (int qp = 0; qp < 4; qp++) {
                    int nts = (qh*8 + qp*2) * 2 + par + bsel;
                    uint32_t boff = (uint32_t)(nts * 8 + brow8) * 128u
                                  + (uint32_t)(ks*16 + bkoff) * 2u;
                    uint32_t bl4[4];
                    ldsm_x4(bl4, smb + SM_B + 32768u + SWZ(boff));
                    mma16816(acc[qp*2],     ah[ks], bl4);
                    mma16816(acc[qp*2 + 1], ah[ks], bl4 + 2);
                }
            }
            // drain (no b2)
            #pragma unroll
            for (int g = 0; g < 2; g++) {
                int gn = nb0 + rowg[g];
                float xk[8];
                #pragma unroll
                for (int q = 0; q < 8; q++) xk[q] = 0.f;
                if (gn < NNODES) {
                    float4 a = *(const float4*)(xin + (size_t)gn*64 + c*16 + qh*8);
                    float4 b = *(const float4*)(xin + (size_t)gn*64 + c*16 + qh*8 + 4);
                    xk[0]=a.x*rcs[g]; xk[1]=a.y*rcs[g]; xk[2]=a.z*rcs[g]; xk[3]=a.w*rcs[g];
                    xk[4]=b.x*rcs[g]; xk[5]=b.y*rcs[g]; xk[6]=b.z*rcs[g]; xk[7]=b.w*rcs[g];
                }
                #pragma unroll
                for (int qq = 0; qq < 8; qq++) {
                    y[g][0] = fmaf(xk[qq], acc[qq][g*2],     y[g][0]);
                    y[g][1] = fmaf(xk[qq], acc[qq][g*2 + 1], y[g][1]);
                }
            }
        }

        // store channel result (warp-exclusive, race-free)
        #pragma unroll
        for (int g = 0; g < 2; g++) {
            int gn = nb0 + rowg[g];
            if (gn < NNODES) {
                if (STOREHALF)
                    *(__half2*)(hout + (size_t)gn*64 + c*16 + 8*par + jlo) =
                        __floats2half2_rn(y[g][0], y[g][1]);
                else
                    *(float2*)(fout + (size_t)gn*64 + c*16 + 8*par + jlo) =
                        make_float2(y[g][0], y[g][1]);
            }
        }

        __syncthreads();     // all warps done reading Bl[c] -> Bl buffer free
        if (c < 3) {
            stage_half(smb + SM_B + 32768u,
                       (const char*)g_Bl + (size_t)(ki*4 + c + 1) * 32768, tid);
            CP_COMMIT();     // overlaps next channel's Bh sweeps
        }
    }
}

// ------------------------- scatter-sum over edges (ILP x4, fp16 gather) -----
__global__ void __launch_bounds__(256)
scatter_kernel(const int* __restrict__ ei) {
    const int QE = NEDGES / 4;                       // 800000
    int t = blockIdx.x * blockDim.x + threadIdx.x;
    if (t >= QE * 16) return;
    int e0 = t >> 4, q = t & 15;
    int dst[4], src[4];
    #pragma unroll
    for (int i = 0; i < 4; i++) {
        int e = e0 + i * QE;
        dst[i] = ei[e];
        src[i] = ei[NEDGES + e];
    }
    float4 v[4];
    #pragma unroll
    for (int i = 0; i < 4; i++) {
        uint2 u = *(const uint2*)((const __half*)g_ky + (size_t)src[i] * 64 + q * 4);
        float2 f0 = __half22float2(*(__half2*)&u.x);
        float2 f1 = __half22float2(*(__half2*)&u.y);
        v[i] = make_float4(f0.x, f0.y, f1.x, f1.y);
    }
    #pragma unroll
    for (int i = 0; i < 4; i++)
        atomicAdd(&((float4*)g_sums)[(size_t)dst[i] * 16 + q], v[i]);
    if (q == 0) {
        #pragma unroll
        for (int i = 0; i < 4; i++)
            atomicAdd(&g_cnt[dst[i]], 1.0f);
    }
}

// ------------------------- mix linear: out = v @ mixW^T + mixb --------------
__global__ void __launch_bounds__(256)
mix_kernel(const float* __restrict__ mixW, const float* __restrict__ mixb,
           float* __restrict__ out)
{
    __shared__ float mWs[4096];
    int tid = threadIdx.x;
    for (int i = tid; i < 1024; i += 256)
        ((float4*)mWs)[i] = ((const float4*)mixW)[i];
    __syncthreads();

    int n = blockIdx.x * 128 + (tid >> 1);
    int ob = (tid & 1) * 32;
    if (n >= NNODES) return;
    const float4* v4 = (const float4*)(g_v + (size_t)n * 64);
    const float4* mw4 = (const float4*)mWs;
    float a2[32];
    #pragma unroll
    for (int o = 0; o < 32; o++) a2[o] = 0.f;
    #pragma unroll 4
    for (int v = 0; v < 16; v++) {
        float4 yv = v4[v];
        #pragma unroll
        for (int o = 0; o < 32; o++) {
            float4 w4 = mw4[(ob + o) * 16 + v];
            a2[o] = fmaf(yv.x, w4.x, a2[o]);
            a2[o] = fmaf(yv.y, w4.y, a2[o]);
            a2[o] = fmaf(yv.z, w4.z, a2[o]);
            a2[o] = fmaf(yv.w, w4.w, a2[o]);
        }
    }
    #pragma unroll
    for (int o = 0; o < 32; o++)
        out[(size_t)n * 64 + ob + o] = a2[o] + mixb[ob + o];
}

// -----------------------------------------------------------------------------
extern "C" void kernel_launch(void* const* d_in, const int* in_sizes, int n_in,
                              void* d_out, int out_size)
{
    const float* x    = (const float*)d_in[0];
    const float* ea   = (const float*)d_in[1];
    const int*   ei   = (const int*)  d_in[2];
    const float* k1W1 = (const float*)d_in[3];
    const float* k1b1 = (const float*)d_in[4];
    const float* k1W2 = (const float*)d_in[5];
    const float* k1b2 = (const float*)d_in[6];
    const float* k2W1 = (const float*)d_in[7];
    const float* k2b1 = (const float*)d_in[8];
    const float* k2W2 = (const float*)d_in[9];
    const float* k2b2 = (const float*)d_in[10];
    const float* mixW = (const float*)d_in[11];
    const float* mixb = (const float*)d_in[12];
    float* out = (float*)d_out;

    __half* ky_p = nullptr; float *sums_p = nullptr, *cnt_p = nullptr, *v_p = nullptr;
    cudaGetSymbolAddress((void**)&ky_p,   g_ky);
    cudaGetSymbolAddress((void**)&sums_p, g_sums);
    cudaGetSymbolAddress((void**)&cnt_p,  g_cnt);
    cudaGetSymbolAddress((void**)&v_p,    g_v);

    cudaFuncSetAttribute((const void*)mma_fused<false, true>,
                         cudaFuncAttributeMaxDynamicSharedMemorySize, SM_TOTAL);
    cudaFuncSetAttribute((const void*)mma_fused<true, false>,
                         cudaFuncAttributeMaxDynamicSharedMemorySize, SM_TOTAL);

    const int grid = (NNODES + 63) / 64;      // 1563

    prep_zero<<<(NNODES * 16 + 255) / 256, 256>>>(k1W2, k2W2);

    mma_fused<false, true><<<grid, 256, SM_TOTAL>>>(
        x, ea, k1W1, k1b1, k1b2, nullptr, nullptr, ky_p, 0);

    scatter_kernel<<<(NEDGES / 4 * 16 + 255) / 256, 256>>>(ei);

    mma_fused<true, false><<<grid, 256, SM_TOTAL>>>(
        sums_p, ea, k2W1, k2b1, k2b2, cnt_p, v_p, nullptr, 1);

    mix_kernel<<<(NNODES + 127) / 128, 256>>>(mixW, mixb, out);
}